// round 14
// baseline (speedup 1.0000x reference)
#include <cuda_runtime.h>
#include <math.h>
#include <float.h>

#define B_  16
#define M_  2
#define S_  1024
#define F_  32
#define D_  64
#define H_  4
#define K_  20
#define A_  10
#define HD_ (H_*D_)   /* 256 */
#define BM_ (B_*M_)   /* 32  */
#define NTOK_ (BM_*S_) /* 32768 */

// ---------------- device scratch (static: no runtime allocation) -------------
__device__ float g_h0 [NTOK_*100];          // 13.1 MB
__device__ float g_h1 [NTOK_*100];          // 13.1 MB
__device__ float g_enc[NTOK_*D_];           // 8 MB
__device__ float g_q  [BM_*H_*S_*D_];       // 32 MB
__device__ float g_k  [BM_*H_*S_*D_];       // 32 MB
__device__ float g_mse[M_*H_];

// packed f32x2 helpers (sm_103a FFMA2 — only reachable via PTX)
#define FFMA2(d,a,b,c) asm("fma.rn.f32x2 %0, %1, %2, %3;" : "=l"(d) : "l"(a), "l"(b), "l"(c))
#define FADD2(d,a,b)   asm("add.rn.f32x2 %0, %1, %2;"     : "=l"(d) : "l"(a), "l"(b))
#define PACK2(d,lo,hi) asm("mov.b64 %0, {%1, %2};"        : "=l"(d) : "f"(lo), "f"(hi))
#define UNPACK2(lo,hi,s) asm("mov.b64 {%0, %1}, %2;"      : "=f"(lo), "=f"(hi) : "l"(s))

// ---------------- MLP layer: packed-pair FFMA2 body ---------------------------
// Outer loop over input rows, inner over NGX output groups with packed
// accumulators: per row = 1 PACK + NGX*(1 LDS.128 + 2 FFMA2)  (0.39 slots/MAC).
template<int IN, int NGH_S, int NGX, bool RELU>
__device__ __forceinline__ void mlp_compute(
    const float (&r)[IN], const float4* __restrict__ Wsm,
    const float* __restrict__ bsm, int jg0, float* __restrict__ houtrow)
{
    unsigned long long acc[2*NGX];
    #pragma unroll
    for (int j = 0; j < NGX; j++) {
        PACK2(acc[2*j+0], bsm[(jg0+j)*4+0], bsm[(jg0+j)*4+1]);
        PACK2(acc[2*j+1], bsm[(jg0+j)*4+2], bsm[(jg0+j)*4+3]);
    }
    #pragma unroll 2
    for (int i = 0; i < IN; i++) {
        unsigned long long rr; PACK2(rr, r[i], r[i]);
        const ulonglong2* wrow = (const ulonglong2*)(Wsm + i*NGH_S);
        #pragma unroll
        for (int j = 0; j < NGX; j++) {
            ulonglong2 w = wrow[j];
            FFMA2(acc[2*j+0], rr, w.x, acc[2*j+0]);
            FFMA2(acc[2*j+1], rr, w.y, acc[2*j+1]);
        }
    }
    #pragma unroll
    for (int j = 0; j < NGX; j++) {
        float a0,a1,a2,a3;
        UNPACK2(a0, a1, acc[2*j+0]);
        UNPACK2(a2, a3, acc[2*j+1]);
        if (RELU) {
            a0 = fmaxf(a0, 0.f); a1 = fmaxf(a1, 0.f);
            a2 = fmaxf(a2, 0.f); a3 = fmaxf(a3, 0.f);
        }
        *(float4*)(houtrow + (jg0+j)*4) = make_float4(a0,a1,a2,a3);
    }
}

// grid = (NTOK_/128, 4), 128 threads; thread owns one token; blockIdx.y picks
// an output-column quarter. Only that quarter of W is staged in SMEM.
template<int IN, int OUT, bool RELU>
__global__ void __launch_bounds__(128)
mlp_kernel(const float* __restrict__ hin,
           const float* __restrict__ W,     // (M, IN, OUT)
           const float* __restrict__ bias,  // (M, OUT)
           float* __restrict__ hout)
{
    constexpr int NG   = OUT/4;          // float4 output groups
    constexpr int NGH  = (NG + 3)/4;     // groups per quarter (100->7, 64->4)
    constexpr int TAIL = NG - 3*NGH;     // last quarter (100->4, 64->4)
    __shared__ float4 Wsm[IN*NGH];
    __shared__ float  bsm[OUT];

    const int tid = threadIdx.x;
    const int tok = blockIdx.x*128 + tid;
    const int m   = (tok >> 10) & (M_-1);    // bm = tok/S_, m = bm % M_
    const int jg0 = blockIdx.y * NGH;
    const int ng  = (blockIdx.y < 3) ? NGH : TAIL;

    {
        const float* wb = W + (size_t)m*IN*OUT + jg0*4;
        for (int idx = tid; idx < IN*ng; idx += 128) {
            int i = idx / ng, c = idx - i*ng;
            Wsm[i*NGH + c] = *(const float4*)(wb + i*OUT + c*4);
        }
        for (int i = tid; i < OUT; i += 128) bsm[i] = bias[m*OUT + i];
    }
    __syncthreads();

    float r[IN];
    {
        const float4* hp = (const float4*)(hin + (size_t)tok*IN);
        #pragma unroll
        for (int i = 0; i < IN/4; i++) {
            float4 v = hp[i];
            r[4*i+0]=v.x; r[4*i+1]=v.y; r[4*i+2]=v.z; r[4*i+3]=v.w;
        }
    }

    float* houtrow = hout + (size_t)tok*OUT;
    if (blockIdx.y < 3) mlp_compute<IN, NGH, NGH,  RELU>(r, Wsm, bsm, jg0, houtrow);
    else                mlp_compute<IN, NGH, TAIL, RELU>(r, Wsm, bsm, jg0, houtrow);
}

// ---------------- LN + q/k projections (flat, pass+col split, packed) ---------
// grid = (NTOK_/128, 2, 2): blockIdx.z = q/k pass, blockIdx.y = column half.
// W half staged in 32KB dynamic SMEM; packed FFMA2 over 8-group subtiles.
#define PROJ2_SMEM_FLOATS (D_*(HD_/2) + 128)
#define PROJ2_SMEM_BYTES  (PROJ2_SMEM_FLOATS*4)

__global__ void __launch_bounds__(128)
proj2_kernel(const float* __restrict__ lnqg, const float* __restrict__ lnqb,
             const float* __restrict__ lnkg, const float* __restrict__ lnkb,
             const float* __restrict__ Wq,   const float* __restrict__ bq,
             const float* __restrict__ Wk,   const float* __restrict__ bk)
{
    extern __shared__ float psm[];
    float4* Wsm = (float4*)psm;        // 64 x 32 float4  (32 KB)
    float*  lnA = psm + D_*(HD_/2);    // 128: [0..63]=gamma [64..127]=beta

    const int tid  = threadIdx.x;
    const int tok  = blockIdx.x*128 + tid;
    const int by   = blockIdx.y;            // column half
    const int pass = blockIdx.z;            // 0=q 1=k
    const int bm   = tok >> 10;
    const int s    = tok & (S_-1);
    const int m    = bm & (M_-1);

    {
        const float* gsrc = pass ? lnkg : lnqg;
        const float* bsrc = pass ? lnkb : lnqb;
        lnA[tid] = (tid < 64) ? gsrc[m*D_ + tid] : bsrc[m*D_ + tid - 64];
        const float4* src = (const float4*)((pass ? Wk : Wq) + (size_t)m*D_*HD_);
        for (int idx = tid; idx < D_*32; idx += 128) {
            int i = idx >> 5, c = idx & 31;
            Wsm[i*32 + c] = src[i*64 + by*32 + c];
        }
    }

    float e[D_];
    {
        const float4* ep = (const float4*)(g_enc + (size_t)tok*D_);
        #pragma unroll
        for (int i = 0; i < D_/4; i++) {
            float4 v = ep[i];
            e[4*i+0]=v.x; e[4*i+1]=v.y; e[4*i+2]=v.z; e[4*i+3]=v.w;
        }
    }
    float mu = 0.f;
    #pragma unroll
    for (int d = 0; d < D_; d++) mu += e[d];
    mu *= (1.0f/D_);
    float var = 0.f;
    #pragma unroll
    for (int d = 0; d < D_; d++) { float x = e[d]-mu; var = fmaf(x,x,var); }
    var *= (1.0f/D_);
    const float rstd = rsqrtf(var + 1e-5f);

    __syncthreads();

    #pragma unroll
    for (int d = 0; d < D_; d++)
        e[d] = (e[d]-mu)*rstd * lnA[d] + lnA[64+d];

    const float* bop = (pass ? bk : bq) + m*HD_;
    float* outp      = pass ? g_k : g_q;

    #pragma unroll 1
    for (int st = 0; st < 4; st++) {          // 4 subtiles of 8 groups
        const int G0 = by*32 + st*8;          // global float4-group index
        unsigned long long acc[16];
        #pragma unroll
        for (int j = 0; j < 8; j++) {
            float4 b4 = __ldg((const float4*)(bop + (G0+j)*4));
            PACK2(acc[2*j+0], b4.x, b4.y);
            PACK2(acc[2*j+1], b4.z, b4.w);
        }
        #pragma unroll 2
        for (int i = 0; i < D_; i++) {
            unsigned long long rr; PACK2(rr, e[i], e[i]);
            const ulonglong2* wrow = (const ulonglong2*)(Wsm + i*32 + st*8);
            #pragma unroll
            for (int j = 0; j < 8; j++) {
                ulonglong2 w = wrow[j];
                FFMA2(acc[2*j+0], rr, w.x, acc[2*j+0]);
                FFMA2(acc[2*j+1], rr, w.y, acc[2*j+1]);
            }
        }
        #pragma unroll
        for (int j = 0; j < 8; j++) {
            float a0,a1,a2,a3;
            UNPACK2(a0, a1, acc[2*j+0]);
            UNPACK2(a2, a3, acc[2*j+1]);
            const int G  = G0 + j;
            const int h  = G >> 4;
            const int d0 = (G & 15) * 4;
            *(float4*)(outp + ((size_t)(bm*H_ + h)*S_ + s)*D_ + d0)
                = make_float4(a0,a1,a2,a3);
        }
    }
}

// ---------------- kernel C: scores + top-k + quantiles + outputs -------------
// Fully register-resident top-k: no dynamic indexing anywhere -> no local mem.
__device__ __forceinline__ void topk_insert(float (&tv)[K_], int (&ti)[K_],
                                            float score, int tg)
{
    bool gt[K_];
    #pragma unroll
    for (int i = 0; i < K_; i++) gt[i] = (tv[i] < score);   // strict: stable ties
    #pragma unroll
    for (int i = K_-1; i > 0; i--) {
        if (gt[i-1]) { tv[i] = tv[i-1]; ti[i] = ti[i-1]; }
    }
    #pragma unroll
    for (int i = 0; i < K_; i++) {
        bool place = gt[i] && ((i == 0) || !gt[i-1]);
        if (place) { tv[i] = score; ti[i] = tg; }
    }
}

// grid (BM_*H_, 8), 128 threads. Each thread owns one query row s.
// q pre-scaled by beta=0.125 at load; dot products via packed f32x2 FMA.
// Top-k checks batched over 8-key groups: extract-max while-loop amortizes the
// warp-wide insert-body walks (~2 walks/group vs ~7.7 per-key walks).
__global__ void __launch_bounds__(128, 3)
score_kernel(const float* __restrict__ Y, float* __restrict__ out)
{
    __shared__ float kt [128*D_];   // 32 KB K-tile
    __shared__ float ysm[S_];       // 4 KB  Y row for this (b,m)
    __shared__ float red[128];

    const int tid = threadIdx.x;
    const int bmh = blockIdx.x;
    const int bm  = bmh / H_;
    const int h   = bmh % H_;
    const int b   = bm / M_;
    const int m   = bm % M_;
    const int s   = blockIdx.y*128 + tid;

    // Y row -> smem
    for (int i = tid; i < S_; i += 128) ysm[i] = Y[bm*S_ + i];

    // q row -> packed f32x2 registers, pre-scaled by beta = 1/sqrt(64)
    unsigned long long qU[32];
    {
        const float4* qr = (const float4*)(g_q + ((size_t)(bm*H_ + h)*S_ + s)*D_);
        #pragma unroll
        for (int i = 0; i < 16; i++) {
            float4 v = qr[i];
            v.x *= 0.125f; v.y *= 0.125f; v.z *= 0.125f; v.w *= 0.125f;
            PACK2(qU[2*i+0], v.x, v.y);
            PACK2(qU[2*i+1], v.z, v.w);
        }
    }

    float tv[K_];
    int   ti[K_];
    #pragma unroll
    for (int i = 0; i < K_; i++) { tv[i] = -FLT_MAX; ti[i] = 0; }
    float vmin = -FLT_MAX;

    for (int kt_i = 0; kt_i < S_/128; kt_i++) {
        __syncthreads();
        {
            const float4* src = (const float4*)(g_k + ((size_t)(bm*H_ + h)*S_ + kt_i*128)*D_);
            for (int i = tid; i < (128*D_)>>2; i += 128) ((float4*)kt)[i] = src[i];
        }
        __syncthreads();
        #pragma unroll 1
        for (int tt = 0; tt < 128; tt += 8) {
            float sc[8];
            // two 4-key FFMA2 dot batches
            #pragma unroll
            for (int half = 0; half < 2; half++) {
                const int t0 = tt + half*4;
                const ulonglong2* k0 = (const ulonglong2*)(kt + (t0+0)*D_);
                const ulonglong2* k1 = (const ulonglong2*)(kt + (t0+1)*D_);
                const ulonglong2* k2 = (const ulonglong2*)(kt + (t0+2)*D_);
                const ulonglong2* k3 = (const ulonglong2*)(kt + (t0+3)*D_);
                unsigned long long a0=0ull,b0v=0ull, a1=0ull,b1v=0ull;
                unsigned long long a2=0ull,b2v=0ull, a3=0ull,b3v=0ull;
                #pragma unroll
                for (int i = 0; i < 16; i++) {
                    ulonglong2 v0 = k0[i];
                    ulonglong2 v1 = k1[i];
                    ulonglong2 v2 = k2[i];
                    ulonglong2 v3 = k3[i];
                    FFMA2(a0,  qU[2*i+0], v0.x, a0);
                    FFMA2(b0v, qU[2*i+1], v0.y, b0v);
                    FFMA2(a1,  qU[2*i+0], v1.x, a1);
                    FFMA2(b1v, qU[2*i+1], v1.y, b1v);
                    FFMA2(a2,  qU[2*i+0], v2.x, a2);
                    FFMA2(b2v, qU[2*i+1], v2.y, b2v);
                    FFMA2(a3,  qU[2*i+0], v3.x, a3);
                    FFMA2(b3v, qU[2*i+1], v3.y, b3v);
                }
                FADD2(a0, a0, b0v);
                FADD2(a1, a1, b1v);
                FADD2(a2, a2, b2v);
                FADD2(a3, a3, b3v);
                float l0,h0c, l1,h1c, l2,h2c, l3,h3c;
                UNPACK2(l0, h0c, a0);
                UNPACK2(l1, h1c, a1);
                UNPACK2(l2, h2c, a2);
                UNPACK2(l3, h3c, a3);
                sc[half*4+0] = l0 + h0c;
                sc[half*4+1] = l1 + h1c;
                sc[half*4+2] = l2 + h2c;
                sc[half*4+3] = l3 + h3c;
            }

            // group max with index (strict >: earliest index wins on ties)
            float m0 = fmaxf(sc[0], sc[1]); int j0 = (sc[1] > sc[0]) ? 1 : 0;
            float m1 = fmaxf(sc[2], sc[3]); int j1 = (sc[3] > sc[2]) ? 3 : 2;
            float m2 = fmaxf(sc[4], sc[5]); int j2 = (sc[5] > sc[4]) ? 5 : 4;
            float m3 = fmaxf(sc[6], sc[7]); int j3 = (sc[7] > sc[6]) ? 7 : 6;
            float n0 = fmaxf(m0, m1);  int p0 = (m1 > m0) ? j1 : j0;
            float n1 = fmaxf(m2, m3);  int p1 = (m3 > m2) ? j3 : j2;
            float gm = fmaxf(n0, n1);  int gi = (n1 > n0) ? p1 : p0;

            const int base = kt_i*128 + tt;
            while (gm > vmin) {
                topk_insert(tv, ti, gm, base + gi);
                vmin = tv[K_-1];
                // mask out the extracted element (static-index predicated)
                #pragma unroll
                for (int j = 0; j < 8; j++) {
                    if (j == gi) sc[j] = -FLT_MAX;
                }
                // recompute group max
                m0 = fmaxf(sc[0], sc[1]); j0 = (sc[1] > sc[0]) ? 1 : 0;
                m1 = fmaxf(sc[2], sc[3]); j1 = (sc[3] > sc[2]) ? 3 : 2;
                m2 = fmaxf(sc[4], sc[5]); j2 = (sc[5] > sc[4]) ? 5 : 4;
                m3 = fmaxf(sc[6], sc[7]); j3 = (sc[7] > sc[6]) ? 7 : 6;
                n0 = fmaxf(m0, m1);  p0 = (m1 > m0) ? j1 : j0;
                n1 = fmaxf(m2, m3);  p1 = (m3 > m2) ? j3 : j2;
                gm = fmaxf(n0, n1);  gi = (n1 > n0) ? p1 : p0;
            }
        }
    }

    // gather selected Y values (static indices after unroll)
    float yv[K_];
    #pragma unroll
    for (int i = 0; i < K_; i++) yv[i] = ysm[ti[i]];

    // ascending sort: fully unrolled bubble network (static indices only)
    #pragma unroll
    for (int i = 0; i < K_-1; i++) {
        #pragma unroll
        for (int j = 0; j < K_-1-i; j++) {
            float a = yv[j], c = yv[j+1];
            yv[j]   = fminf(a, c);
            yv[j+1] = fmaxf(a, c);
        }
    }

    // 20 quantiles, compile-time positions (pos = q*(K-1)), y_pred = mean
    constexpr float QS[2*A_] = {
        0.025f,0.03f,0.04f,0.05f,0.06f,0.07f,0.075f,0.085f,0.095f,0.1f,
        0.975f,0.97f,0.96f,0.95f,0.94f,0.93f,0.925f,0.915f,0.905f,0.9f };
    float qv[2*A_];
    float qsum = 0.f;
    #pragma unroll
    for (int i = 0; i < 2*A_; i++) {
        const float hp = QS[i] * (float)(K_-1);
        const int   lo = ((int)hp > K_-2) ? (K_-2) : (int)hp;
        const float fr = hp - (float)lo;
        float v = yv[lo] + (yv[lo+1] - yv[lo]) * fr;
        qv[i] = v; qsum += v;
    }
    float ypred = qsum * (1.0f/(2*A_));

    // scatter quantile outputs: [h][b][a][s][m]
    float* out_low  = out + M_ + B_*S_*M_;
    float* out_high = out_low + (size_t)H_*B_*A_*S_*M_;
    #pragma unroll
    for (int a = 0; a < A_; a++) {
        size_t off = (((size_t)((h*B_ + b)*A_ + a))*S_ + s)*M_ + m;
        out_low [off] = qv[a];
        out_high[off] = qv[a + A_];
    }

    // MSE accumulation for scores_out
    float yt = ysm[s];
    float d  = yt - ypred;
    red[tid] = d*d;
    __syncthreads();
    for (int off = 64; off > 0; off >>= 1) {
        if (tid < off) red[tid] += red[tid+off];
        __syncthreads();
    }
    if (tid == 0) atomicAdd(&g_mse[m*H_ + h], red[0]);
}

// ---------------- small kernels ----------------------------------------------
__global__ void init_kernel()
{
    if (threadIdx.x < M_*H_) g_mse[threadIdx.x] = 0.f;
}

__global__ void finalize_kernel(float* __restrict__ out)
{
    if (threadIdx.x < M_) {
        int m = threadIdx.x;
        float sacc = 0.f;
        for (int h = 0; h < H_; h++) sacc += g_mse[m*H_ + h];
        out[m] = sacc / (float)(B_*S_*H_);
    }
}

__global__ void yout_kernel(const float* __restrict__ Y, float* __restrict__ out)
{
    int i = blockIdx.x*blockDim.x + threadIdx.x;
    if (i < B_*S_*M_) {
        int m = i % M_;
        int s = (i / M_) % S_;
        int b = i / (M_*S_);
        out[M_ + i] = Y[((size_t)(b*M_ + m))*S_ + s];
    }
}

// ---------------- launch ------------------------------------------------------
extern "C" void kernel_launch(void* const* d_in, const int* in_sizes, int n_in,
                              void* d_out, int out_size)
{
    (void)in_sizes; (void)n_in; (void)out_size;
    const float* X    = (const float*)d_in[0];
    const float* Y    = (const float*)d_in[1];
    const float* W0   = (const float*)d_in[2];
    const float* b0   = (const float*)d_in[3];
    const float* W1   = (const float*)d_in[4];
    const float* b1   = (const float*)d_in[5];
    const float* W2   = (const float*)d_in[6];
    const float* b2   = (const float*)d_in[7];
    const float* W3   = (const float*)d_in[8];
    const float* b3   = (const float*)d_in[9];
    const float* lnqg = (const float*)d_in[10];
    const float* lnqb = (const float*)d_in[11];
    const float* lnkg = (const float*)d_in[12];
    const float* lnkb = (const float*)d_in[13];
    const float* Wq   = (const float*)d_in[14];
    const float* bq   = (const float*)d_in[15];
    const float* Wk   = (const float*)d_in[16];
    const float* bk   = (const float*)d_in[17];
    float* out = (float*)d_out;

    cudaFuncSetAttribute(proj2_kernel, cudaFuncAttributeMaxDynamicSharedMemorySize, PROJ2_SMEM_BYTES);

    float* h0p; cudaGetSymbolAddress((void**)&h0p, g_h0);
    float* h1p; cudaGetSymbolAddress((void**)&h1p, g_h1);
    float* enp; cudaGetSymbolAddress((void**)&enp, g_enc);

    const int NB = NTOK_/128;   // 256 blocks
    dim3 gm(NB, 4);
    dim3 gp(NB, 2, 2);

    init_kernel<<<1, 32>>>();
    mlp_kernel<F_, 100, true ><<<gm, 128>>>(X,   W0, b0, h0p);
    mlp_kernel<100, 100, true ><<<gm, 128>>>(h0p, W1, b1, h1p);
    mlp_kernel<100, 100, true ><<<gm, 128>>>(h1p, W2, b2, h0p);
    mlp_kernel<100, D_, false><<<gm, 128>>>(h0p, W3, b3, enp);
    proj2_kernel<<<gp, 128, PROJ2_SMEM_BYTES>>>(lnqg,lnqb, lnkg,lnkb, Wq,bq, Wk,bk);
    dim3 gc(BM_*H_, S_/128);
    score_kernel<<<gc, 128>>>(Y, out);
    finalize_kernel<<<1, 32>>>(out);
    yout_kernel<<<(B_*S_*M_ + 255)/256, 256>>>(Y, out);
}

// round 15
// speedup vs baseline: 1.0512x; 1.0512x over previous
#include <cuda_runtime.h>
#include <math.h>
#include <float.h>

#define B_  16
#define M_  2
#define S_  1024
#define F_  32
#define D_  64
#define H_  4
#define K_  20
#define A_  10
#define HD_ (H_*D_)   /* 256 */
#define BM_ (B_*M_)   /* 32  */
#define NTOK_ (BM_*S_) /* 32768 */

// ---------------- device scratch (static: no runtime allocation) -------------
__device__ float g_h0 [NTOK_*100];          // 13.1 MB
__device__ float g_h1 [NTOK_*100];          // 13.1 MB
__device__ float g_enc[NTOK_*D_];           // 8 MB
__device__ float g_q  [BM_*H_*S_*D_];       // 32 MB
__device__ float g_k  [BM_*H_*S_*D_];       // 32 MB
__device__ float g_mse[M_*H_];

// packed f32x2 helpers (sm_103a FFMA2 — only reachable via PTX)
#define FFMA2(d,a,b,c) asm("fma.rn.f32x2 %0, %1, %2, %3;" : "=l"(d) : "l"(a), "l"(b), "l"(c))
#define FADD2(d,a,b)   asm("add.rn.f32x2 %0, %1, %2;"     : "=l"(d) : "l"(a), "l"(b))
#define PACK2(d,lo,hi) asm("mov.b64 %0, {%1, %2};"        : "=l"(d) : "f"(lo), "f"(hi))
#define UNPACK2(lo,hi,s) asm("mov.b64 {%0, %1}, %2;"      : "=f"(lo), "=f"(hi) : "l"(s))

// ---------------- MLP layer: 2-way output split + jg-pair FFMA2 ---------------
// grid = (NTOK_/128, 2), 128 threads; thread owns one token; blockIdx.y picks
// an output-column half (r[] reused ~ng times -> stays register-resident).
// Pair body per input row: 1 PACK + 2 LDS.128 + 4 FFMA2 = 7 slots / 16 MACs.
template<int IN, int OUT, bool RELU>
__global__ void __launch_bounds__(128)
mlp_kernel(const float* __restrict__ hin,
           const float* __restrict__ W,     // (M, IN, OUT)
           const float* __restrict__ bias,  // (M, OUT)
           float* __restrict__ hout)
{
    constexpr int NG  = OUT/4;        // float4 output groups
    constexpr int NGH = (NG+1)/2;     // groups in half 0 (>= half 1)
    __shared__ float4 Wsm[IN*NGH];
    __shared__ float  bsm[OUT];

    const int tid = threadIdx.x;
    const int tok = blockIdx.x*128 + tid;
    const int m   = (tok >> 10) & (M_-1);    // bm = tok/S_, m = bm % M_
    const int jg0 = blockIdx.y * NGH;
    const int ng  = blockIdx.y ? (NG - NGH) : NGH;

    {
        const float* wb = W + (size_t)m*IN*OUT + jg0*4;
        for (int idx = tid; idx < IN*ng; idx += 128) {
            int i = idx / ng, c = idx - i*ng;
            Wsm[i*NGH + c] = *(const float4*)(wb + i*OUT + c*4);
        }
        for (int i = tid; i < OUT; i += 128) bsm[i] = bias[m*OUT + i];
    }
    __syncthreads();

    float r[IN];
    {
        const float4* hp = (const float4*)(hin + (size_t)tok*IN);
        #pragma unroll
        for (int i = 0; i < IN/4; i++) {
            float4 v = hp[i];
            r[4*i+0]=v.x; r[4*i+1]=v.y; r[4*i+2]=v.z; r[4*i+3]=v.w;
        }
    }

    float* houtrow = hout + (size_t)tok*OUT;

    int jg = 0;
    #pragma unroll 1
    for (; jg + 1 < ng; jg += 2) {       // pairs of output groups
        unsigned long long acc[4];
        PACK2(acc[0], bsm[(jg0+jg)*4+0],   bsm[(jg0+jg)*4+1]);
        PACK2(acc[1], bsm[(jg0+jg)*4+2],   bsm[(jg0+jg)*4+3]);
        PACK2(acc[2], bsm[(jg0+jg+1)*4+0], bsm[(jg0+jg+1)*4+1]);
        PACK2(acc[3], bsm[(jg0+jg+1)*4+2], bsm[(jg0+jg+1)*4+3]);
        #pragma unroll
        for (int i = 0; i < IN; i++) {
            unsigned long long rr; PACK2(rr, r[i], r[i]);
            ulonglong2 w0 = *(const ulonglong2*)(Wsm + i*NGH + jg);
            ulonglong2 w1 = *(const ulonglong2*)(Wsm + i*NGH + jg + 1);
            FFMA2(acc[0], rr, w0.x, acc[0]);
            FFMA2(acc[1], rr, w0.y, acc[1]);
            FFMA2(acc[2], rr, w1.x, acc[2]);
            FFMA2(acc[3], rr, w1.y, acc[3]);
        }
        #pragma unroll
        for (int p = 0; p < 2; p++) {
            float a0,a1,a2,a3;
            UNPACK2(a0, a1, acc[2*p+0]);
            UNPACK2(a2, a3, acc[2*p+1]);
            if (RELU) {
                a0 = fmaxf(a0, 0.f); a1 = fmaxf(a1, 0.f);
                a2 = fmaxf(a2, 0.f); a3 = fmaxf(a3, 0.f);
            }
            *(float4*)(houtrow + (jg0+jg+p)*4) = make_float4(a0,a1,a2,a3);
        }
    }
    if (jg < ng) {                        // odd tail group
        unsigned long long acc[2];
        PACK2(acc[0], bsm[(jg0+jg)*4+0], bsm[(jg0+jg)*4+1]);
        PACK2(acc[1], bsm[(jg0+jg)*4+2], bsm[(jg0+jg)*4+3]);
        #pragma unroll
        for (int i = 0; i < IN; i++) {
            unsigned long long rr; PACK2(rr, r[i], r[i]);
            ulonglong2 w0 = *(const ulonglong2*)(Wsm + i*NGH + jg);
            FFMA2(acc[0], rr, w0.x, acc[0]);
            FFMA2(acc[1], rr, w0.y, acc[1]);
        }
        float a0,a1,a2,a3;
        UNPACK2(a0, a1, acc[0]);
        UNPACK2(a2, a3, acc[1]);
        if (RELU) {
            a0 = fmaxf(a0, 0.f); a1 = fmaxf(a1, 0.f);
            a2 = fmaxf(a2, 0.f); a3 = fmaxf(a3, 0.f);
        }
        *(float4*)(houtrow + (jg0+jg)*4) = make_float4(a0,a1,a2,a3);
    }
}

// ---------------- LN + q/k projections (flat, pass+col split, packed) ---------
// grid = (NTOK_/128, 2, 2): blockIdx.z = q/k pass, blockIdx.y = column half.
// W half staged in 32KB dynamic SMEM; packed FFMA2 over 8-group subtiles.
#define PROJ2_SMEM_FLOATS (D_*(HD_/2) + 128)
#define PROJ2_SMEM_BYTES  (PROJ2_SMEM_FLOATS*4)

__global__ void __launch_bounds__(128)
proj2_kernel(const float* __restrict__ lnqg, const float* __restrict__ lnqb,
             const float* __restrict__ lnkg, const float* __restrict__ lnkb,
             const float* __restrict__ Wq,   const float* __restrict__ bq,
             const float* __restrict__ Wk,   const float* __restrict__ bk)
{
    extern __shared__ float psm[];
    float4* Wsm = (float4*)psm;        // 64 x 32 float4  (32 KB)
    float*  lnA = psm + D_*(HD_/2);    // 128: [0..63]=gamma [64..127]=beta

    const int tid  = threadIdx.x;
    const int tok  = blockIdx.x*128 + tid;
    const int by   = blockIdx.y;            // column half
    const int pass = blockIdx.z;            // 0=q 1=k
    const int bm   = tok >> 10;
    const int s    = tok & (S_-1);
    const int m    = bm & (M_-1);

    {
        const float* gsrc = pass ? lnkg : lnqg;
        const float* bsrc = pass ? lnkb : lnqb;
        lnA[tid] = (tid < 64) ? gsrc[m*D_ + tid] : bsrc[m*D_ + tid - 64];
        const float4* src = (const float4*)((pass ? Wk : Wq) + (size_t)m*D_*HD_);
        for (int idx = tid; idx < D_*32; idx += 128) {
            int i = idx >> 5, c = idx & 31;
            Wsm[i*32 + c] = src[i*64 + by*32 + c];
        }
    }

    float e[D_];
    {
        const float4* ep = (const float4*)(g_enc + (size_t)tok*D_);
        #pragma unroll
        for (int i = 0; i < D_/4; i++) {
            float4 v = ep[i];
            e[4*i+0]=v.x; e[4*i+1]=v.y; e[4*i+2]=v.z; e[4*i+3]=v.w;
        }
    }
    float mu = 0.f;
    #pragma unroll
    for (int d = 0; d < D_; d++) mu += e[d];
    mu *= (1.0f/D_);
    float var = 0.f;
    #pragma unroll
    for (int d = 0; d < D_; d++) { float x = e[d]-mu; var = fmaf(x,x,var); }
    var *= (1.0f/D_);
    const float rstd = rsqrtf(var + 1e-5f);

    __syncthreads();

    #pragma unroll
    for (int d = 0; d < D_; d++)
        e[d] = (e[d]-mu)*rstd * lnA[d] + lnA[64+d];

    const float* bop = (pass ? bk : bq) + m*HD_;
    float* outp      = pass ? g_k : g_q;

    #pragma unroll 1
    for (int st = 0; st < 4; st++) {          // 4 subtiles of 8 groups
        const int G0 = by*32 + st*8;          // global float4-group index
        unsigned long long acc[16];
        #pragma unroll
        for (int j = 0; j < 8; j++) {
            float4 b4 = __ldg((const float4*)(bop + (G0+j)*4));
            PACK2(acc[2*j+0], b4.x, b4.y);
            PACK2(acc[2*j+1], b4.z, b4.w);
        }
        #pragma unroll 2
        for (int i = 0; i < D_; i++) {
            unsigned long long rr; PACK2(rr, e[i], e[i]);
            const ulonglong2* wrow = (const ulonglong2*)(Wsm + i*32 + st*8);
            #pragma unroll
            for (int j = 0; j < 8; j++) {
                ulonglong2 w = wrow[j];
                FFMA2(acc[2*j+0], rr, w.x, acc[2*j+0]);
                FFMA2(acc[2*j+1], rr, w.y, acc[2*j+1]);
            }
        }
        #pragma unroll
        for (int j = 0; j < 8; j++) {
            float a0,a1,a2,a3;
            UNPACK2(a0, a1, acc[2*j+0]);
            UNPACK2(a2, a3, acc[2*j+1]);
            const int G  = G0 + j;
            const int h  = G >> 4;
            const int d0 = (G & 15) * 4;
            *(float4*)(outp + ((size_t)(bm*H_ + h)*S_ + s)*D_ + d0)
                = make_float4(a0,a1,a2,a3);
        }
    }
}

// ---------------- kernel C: scores + top-k + quantiles + outputs -------------
// Fully register-resident top-k: no dynamic indexing anywhere -> no local mem.
__device__ __forceinline__ void topk_insert(float (&tv)[K_], int (&ti)[K_],
                                            float score, int tg)
{
    bool gt[K_];
    #pragma unroll
    for (int i = 0; i < K_; i++) gt[i] = (tv[i] < score);   // strict: stable ties
    #pragma unroll
    for (int i = K_-1; i > 0; i--) {
        if (gt[i-1]) { tv[i] = tv[i-1]; ti[i] = ti[i-1]; }
    }
    #pragma unroll
    for (int i = 0; i < K_; i++) {
        bool place = gt[i] && ((i == 0) || !gt[i-1]);
        if (place) { tv[i] = score; ti[i] = tg; }
    }
}

// grid (BM_*H_, 8), 128 threads. Each thread owns one query row s.
// q pre-scaled by beta=0.125 at load; dot products via packed f32x2 FMA.
// Top-k checks batched over 8-key groups: extract-max while-loop amortizes the
// warp-wide insert-body walks (~2 walks/group vs ~7.7 per-key walks).
__global__ void __launch_bounds__(128, 3)
score_kernel(const float* __restrict__ Y, float* __restrict__ out)
{
    __shared__ float kt [128*D_];   // 32 KB K-tile
    __shared__ float ysm[S_];       // 4 KB  Y row for this (b,m)
    __shared__ float red[128];

    const int tid = threadIdx.x;
    const int bmh = blockIdx.x;
    const int bm  = bmh / H_;
    const int h   = bmh % H_;
    const int b   = bm / M_;
    const int m   = bm % M_;
    const int s   = blockIdx.y*128 + tid;

    // Y row -> smem
    for (int i = tid; i < S_; i += 128) ysm[i] = Y[bm*S_ + i];

    // q row -> packed f32x2 registers, pre-scaled by beta = 1/sqrt(64)
    unsigned long long qU[32];
    {
        const float4* qr = (const float4*)(g_q + ((size_t)(bm*H_ + h)*S_ + s)*D_);
        #pragma unroll
        for (int i = 0; i < 16; i++) {
            float4 v = qr[i];
            v.x *= 0.125f; v.y *= 0.125f; v.z *= 0.125f; v.w *= 0.125f;
            PACK2(qU[2*i+0], v.x, v.y);
            PACK2(qU[2*i+1], v.z, v.w);
        }
    }

    float tv[K_];
    int   ti[K_];
    #pragma unroll
    for (int i = 0; i < K_; i++) { tv[i] = -FLT_MAX; ti[i] = 0; }
    float vmin = -FLT_MAX;

    for (int kt_i = 0; kt_i < S_/128; kt_i++) {
        __syncthreads();
        {
            const float4* src = (const float4*)(g_k + ((size_t)(bm*H_ + h)*S_ + kt_i*128)*D_);
            for (int i = tid; i < (128*D_)>>2; i += 128) ((float4*)kt)[i] = src[i];
        }
        __syncthreads();
        #pragma unroll 1
        for (int tt = 0; tt < 128; tt += 8) {
            float sc[8];
            // two 4-key FFMA2 dot batches
            #pragma unroll
            for (int half = 0; half < 2; half++) {
                const int t0 = tt + half*4;
                const ulonglong2* k0 = (const ulonglong2*)(kt + (t0+0)*D_);
                const ulonglong2* k1 = (const ulonglong2*)(kt + (t0+1)*D_);
                const ulonglong2* k2 = (const ulonglong2*)(kt + (t0+2)*D_);
                const ulonglong2* k3 = (const ulonglong2*)(kt + (t0+3)*D_);
                unsigned long long a0=0ull,b0v=0ull, a1=0ull,b1v=0ull;
                unsigned long long a2=0ull,b2v=0ull, a3=0ull,b3v=0ull;
                #pragma unroll
                for (int i = 0; i < 16; i++) {
                    ulonglong2 v0 = k0[i];
                    ulonglong2 v1 = k1[i];
                    ulonglong2 v2 = k2[i];
                    ulonglong2 v3 = k3[i];
                    FFMA2(a0,  qU[2*i+0], v0.x, a0);
                    FFMA2(b0v, qU[2*i+1], v0.y, b0v);
                    FFMA2(a1,  qU[2*i+0], v1.x, a1);
                    FFMA2(b1v, qU[2*i+1], v1.y, b1v);
                    FFMA2(a2,  qU[2*i+0], v2.x, a2);
                    FFMA2(b2v, qU[2*i+1], v2.y, b2v);
                    FFMA2(a3,  qU[2*i+0], v3.x, a3);
                    FFMA2(b3v, qU[2*i+1], v3.y, b3v);
                }
                FADD2(a0, a0, b0v);
                FADD2(a1, a1, b1v);
                FADD2(a2, a2, b2v);
                FADD2(a3, a3, b3v);
                float l0,h0c, l1,h1c, l2,h2c, l3,h3c;
                UNPACK2(l0, h0c, a0);
                UNPACK2(l1, h1c, a1);
                UNPACK2(l2, h2c, a2);
                UNPACK2(l3, h3c, a3);
                sc[half*4+0] = l0 + h0c;
                sc[half*4+1] = l1 + h1c;
                sc[half*4+2] = l2 + h2c;
                sc[half*4+3] = l3 + h3c;
            }

            // group max with index (strict >: earliest index wins on ties)
            float m0 = fmaxf(sc[0], sc[1]); int j0 = (sc[1] > sc[0]) ? 1 : 0;
            float m1 = fmaxf(sc[2], sc[3]); int j1 = (sc[3] > sc[2]) ? 3 : 2;
            float m2 = fmaxf(sc[4], sc[5]); int j2 = (sc[5] > sc[4]) ? 5 : 4;
            float m3 = fmaxf(sc[6], sc[7]); int j3 = (sc[7] > sc[6]) ? 7 : 6;
            float n0 = fmaxf(m0, m1);  int p0 = (m1 > m0) ? j1 : j0;
            float n1 = fmaxf(m2, m3);  int p1 = (m3 > m2) ? j3 : j2;
            float gm = fmaxf(n0, n1);  int gi = (n1 > n0) ? p1 : p0;

            const int base = kt_i*128 + tt;
            while (gm > vmin) {
                topk_insert(tv, ti, gm, base + gi);
                vmin = tv[K_-1];
                // mask out the extracted element (static-index predicated)
                #pragma unroll
                for (int j = 0; j < 8; j++) {
                    if (j == gi) sc[j] = -FLT_MAX;
                }
                // recompute group max
                m0 = fmaxf(sc[0], sc[1]); j0 = (sc[1] > sc[0]) ? 1 : 0;
                m1 = fmaxf(sc[2], sc[3]); j1 = (sc[3] > sc[2]) ? 3 : 2;
                m2 = fmaxf(sc[4], sc[5]); j2 = (sc[5] > sc[4]) ? 5 : 4;
                m3 = fmaxf(sc[6], sc[7]); j3 = (sc[7] > sc[6]) ? 7 : 6;
                n0 = fmaxf(m0, m1);  p0 = (m1 > m0) ? j1 : j0;
                n1 = fmaxf(m2, m3);  p1 = (m3 > m2) ? j3 : j2;
                gm = fmaxf(n0, n1);  gi = (n1 > n0) ? p1 : p0;
            }
        }
    }

    // gather selected Y values (static indices after unroll)
    float yv[K_];
    #pragma unroll
    for (int i = 0; i < K_; i++) yv[i] = ysm[ti[i]];

    // ascending sort: fully unrolled bubble network (static indices only)
    #pragma unroll
    for (int i = 0; i < K_-1; i++) {
        #pragma unroll
        for (int j = 0; j < K_-1-i; j++) {
            float a = yv[j], c = yv[j+1];
            yv[j]   = fminf(a, c);
            yv[j+1] = fmaxf(a, c);
        }
    }

    // 20 quantiles, compile-time positions (pos = q*(K-1)), y_pred = mean
    constexpr float QS[2*A_] = {
        0.025f,0.03f,0.04f,0.05f,0.06f,0.07f,0.075f,0.085f,0.095f,0.1f,
        0.975f,0.97f,0.96f,0.95f,0.94f,0.93f,0.925f,0.915f,0.905f,0.9f };
    float qv[2*A_];
    float qsum = 0.f;
    #pragma unroll
    for (int i = 0; i < 2*A_; i++) {
        const float hp = QS[i] * (float)(K_-1);
        const int   lo = ((int)hp > K_-2) ? (K_-2) : (int)hp;
        const float fr = hp - (float)lo;
        float v = yv[lo] + (yv[lo+1] - yv[lo]) * fr;
        qv[i] = v; qsum += v;
    }
    float ypred = qsum * (1.0f/(2*A_));

    // scatter quantile outputs: [h][b][a][s][m]
    float* out_low  = out + M_ + B_*S_*M_;
    float* out_high = out_low + (size_t)H_*B_*A_*S_*M_;
    #pragma unroll
    for (int a = 0; a < A_; a++) {
        size_t off = (((size_t)((h*B_ + b)*A_ + a))*S_ + s)*M_ + m;
        out_low [off] = qv[a];
        out_high[off] = qv[a + A_];
    }

    // MSE accumulation for scores_out
    float yt = ysm[s];
    float d  = yt - ypred;
    red[tid] = d*d;
    __syncthreads();
    for (int off = 64; off > 0; off >>= 1) {
        if (tid < off) red[tid] += red[tid+off];
        __syncthreads();
    }
    if (tid == 0) atomicAdd(&g_mse[m*H_ + h], red[0]);
}

// ---------------- small kernels ----------------------------------------------
__global__ void init_kernel()
{
    if (threadIdx.x < M_*H_) g_mse[threadIdx.x] = 0.f;
}

__global__ void finalize_kernel(float* __restrict__ out)
{
    if (threadIdx.x < M_) {
        int m = threadIdx.x;
        float sacc = 0.f;
        for (int h = 0; h < H_; h++) sacc += g_mse[m*H_ + h];
        out[m] = sacc / (float)(B_*S_*H_);
    }
}

__global__ void yout_kernel(const float* __restrict__ Y, float* __restrict__ out)
{
    int i = blockIdx.x*blockDim.x + threadIdx.x;
    if (i < B_*S_*M_) {
        int m = i % M_;
        int s = (i / M_) % S_;
        int b = i / (M_*S_);
        out[M_ + i] = Y[((size_t)(b*M_ + m))*S_ + s];
    }
}

// ---------------- launch ------------------------------------------------------
extern "C" void kernel_launch(void* const* d_in, const int* in_sizes, int n_in,
                              void* d_out, int out_size)
{
    (void)in_sizes; (void)n_in; (void)out_size;
    const float* X    = (const float*)d_in[0];
    const float* Y    = (const float*)d_in[1];
    const float* W0   = (const float*)d_in[2];
    const float* b0   = (const float*)d_in[3];
    const float* W1   = (const float*)d_in[4];
    const float* b1   = (const float*)d_in[5];
    const float* W2   = (const float*)d_in[6];
    const float* b2   = (const float*)d_in[7];
    const float* W3   = (const float*)d_in[8];
    const float* b3   = (const float*)d_in[9];
    const float* lnqg = (const float*)d_in[10];
    const float* lnqb = (const float*)d_in[11];
    const float* lnkg = (const float*)d_in[12];
    const float* lnkb = (const float*)d_in[13];
    const float* Wq   = (const float*)d_in[14];
    const float* bq   = (const float*)d_in[15];
    const float* Wk   = (const float*)d_in[16];
    const float* bk   = (const float*)d_in[17];
    float* out = (float*)d_out;

    cudaFuncSetAttribute(proj2_kernel, cudaFuncAttributeMaxDynamicSharedMemorySize, PROJ2_SMEM_BYTES);

    float* h0p; cudaGetSymbolAddress((void**)&h0p, g_h0);
    float* h1p; cudaGetSymbolAddress((void**)&h1p, g_h1);
    float* enp; cudaGetSymbolAddress((void**)&enp, g_enc);

    const int NB = NTOK_/128;   // 256 blocks
    dim3 gm(NB, 2);
    dim3 gp(NB, 2, 2);

    init_kernel<<<1, 32>>>();
    mlp_kernel<F_, 100, true ><<<gm, 128>>>(X,   W0, b0, h0p);
    mlp_kernel<100, 100, true ><<<gm, 128>>>(h0p, W1, b1, h1p);
    mlp_kernel<100, 100, true ><<<gm, 128>>>(h1p, W2, b2, h0p);
    mlp_kernel<100, D_, false><<<gm, 128>>>(h0p, W3, b3, enp);
    proj2_kernel<<<gp, 128, PROJ2_SMEM_BYTES>>>(lnqg,lnqb, lnkg,lnkb, Wq,bq, Wk,bk);
    dim3 gc(BM_*H_, S_/128);
    score_kernel<<<gc, 128>>>(Y, out);
    finalize_kernel<<<1, 32>>>(out);
    yout_kernel<<<(B_*S_*M_ + 255)/256, 256>>>(Y, out);
}